// round 5
// baseline (speedup 1.0000x reference)
#include <cuda_runtime.h>
#include <cuda_bf16.h>
#include <cstdint>

#define GR 8
#define BATCH 32
#define TT 512
#define ROWS 384          // 3 * 128
#define PADW 386          // phase-1 weight smem row stride (floats)
#define XROW 132          // phase-1 x smem row stride (floats)
#define HPAD 144          // phase-2 h buffer stride (4 chunks of 32, stride 36)

typedef unsigned long long ull;

// 201 MB scratch for gx[t][g][o][b]
__device__ float g_gx[(size_t)TT * GR * ROWS * BATCH];

__device__ __forceinline__ ull pk(float lo, float hi) {
    ull r;
    asm("mov.b64 %0, {%1, %2};" : "=l"(r) : "f"(lo), "f"(hi));
    return r;
}
__device__ __forceinline__ float2 up(ull v) {
    float2 r;
    asm("mov.b64 {%0, %1}, %2;" : "=f"(r.x), "=f"(r.y) : "l"(v));
    return r;
}
__device__ __forceinline__ void fma2(ull& d, ull a, ull b) {
    asm("fma.rn.f32x2 %0, %1, %2, %0;" : "+l"(d) : "l"(a), "l"(b));
}
__device__ __forceinline__ float sigm(float x) {
    return __fdividef(1.0f, 1.0f + __expf(-x));
}
__device__ __forceinline__ float tanh_(float x) {
    return 1.0f - __fdividef(2.0f, __expf(2.0f * x) + 1.0f);
}
__device__ __forceinline__ float hadd(ull v) {
    float2 u = up(v);
    return u.x + u.y;
}
__device__ __forceinline__ unsigned sptr(const void* p) {
    return (unsigned)__cvta_generic_to_shared(p);
}
__device__ __forceinline__ void cpa8(unsigned d, const void* s) {
    asm volatile("cp.async.ca.shared.global [%0], [%1], 8;" :: "r"(d), "l"(s));
}
__device__ __forceinline__ void cpa16(unsigned d, const void* s) {
    asm volatile("cp.async.cg.shared.global [%0], [%1], 16;" :: "r"(d), "l"(s));
}
__device__ __forceinline__ void cpcommit() { asm volatile("cp.async.commit_group;" ::: "memory"); }
__device__ __forceinline__ void cpwait0()  { asm volatile("cp.async.wait_group 0;" ::: "memory"); }
__device__ __forceinline__ void cpwait1()  { asm volatile("cp.async.wait_group 1;" ::: "memory"); }

// ============================================================================
// Phase 1: gx[t][g][o][b] = b_ih[g][o] + sum_i W_ih[g][o][i] * x[b][t][g*128+i]
// 128 CTAs = (tb 0..15) x (g 0..7), 512 threads. x staged [b][XROW] via
// cp.async.16, double-buffered; W_ih[g] transposed in smem. (Unchanged R4.)
// ============================================================================
__global__ void __launch_bounds__(512, 1)
gx_kernel(const float* __restrict__ x,
          const float* __restrict__ W_ih,
          const float* __restrict__ b_ih)
{
    extern __shared__ float sm[];
    float* Ws = sm;                       // [128][PADW]  W[k][o]
    float* Xs = sm + 128 * PADW;          // [2][32][XROW] x[b][k]

    const int g  = blockIdx.x & 7;
    const int tb = blockIdx.x >> 3;
    const int tid = threadIdx.x;

    const float* Wg = W_ih + (size_t)g * ROWS * 128;
    for (int idx = tid; idx < ROWS * 128; idx += 512) {
        int o = idx >> 7, k = idx & 127;
        Ws[k * PADW + o] = Wg[idx];
    }

    const int w    = tid >> 5;
    const int lane = tid & 31;
    const int rsub = lane >> 3;           // 0..3
    const int bq   = lane & 7;            // 0..7
    const int ro   = w * 24 + rsub * 6;   // 6 rows per thread

    float bias[6];
#pragma unroll
    for (int i = 0; i < 6; i++) bias[i] = b_ih[g * ROWS + ro + i];

    {
        const int t0 = tb * 32;
#pragma unroll
        for (int r = 0; r < 2; r++) {
            int c = tid + r * 512;
            int b = c >> 5, kq = c & 31;
            cpa16(sptr(Xs + b * XROW + kq * 4),
                  x + ((size_t)b * TT + t0) * 1024 + g * 128 + kq * 4);
        }
    }
    cpcommit();

    for (int tt = 0; tt < 32; tt++) {
        const int t = tb * 32 + tt;
        const float* Xc = Xs + (tt & 1) * (32 * XROW);

        cpwait0();
        __syncthreads();

        if (tt < 31) {
            float* Xn = Xs + ((tt + 1) & 1) * (32 * XROW);
#pragma unroll
            for (int r = 0; r < 2; r++) {
                int c = tid + r * 512;
                int b = c >> 5, kq = c & 31;
                cpa16(sptr(Xn + b * XROW + kq * 4),
                      x + ((size_t)b * TT + t + 1) * 1024 + g * 128 + kq * 4);
            }
        }
        cpcommit();

        ull acc[3][4];
#pragma unroll
        for (int p = 0; p < 3; p++) {
            ull binit = pk(bias[2 * p], bias[2 * p + 1]);
#pragma unroll
            for (int i = 0; i < 4; i++) acc[p][i] = binit;
        }

#pragma unroll 4
        for (int k = 0; k < 128; k++) {
            const float* wb = Ws + k * PADW + ro;
            ull w0 = *(const ull*)(wb);
            ull w1 = *(const ull*)(wb + 2);
            ull w2 = *(const ull*)(wb + 4);
            float x0 = Xc[(bq     ) * XROW + k];
            float x1 = Xc[(bq +  8) * XROW + k];
            float x2 = Xc[(bq + 16) * XROW + k];
            float x3 = Xc[(bq + 24) * XROW + k];
            ull d0 = pk(x0, x0), d1 = pk(x1, x1), d2 = pk(x2, x2), d3 = pk(x3, x3);
            fma2(acc[0][0], w0, d0); fma2(acc[0][1], w0, d1);
            fma2(acc[0][2], w0, d2); fma2(acc[0][3], w0, d3);
            fma2(acc[1][0], w1, d0); fma2(acc[1][1], w1, d1);
            fma2(acc[1][2], w1, d2); fma2(acc[1][3], w1, d3);
            fma2(acc[2][0], w2, d0); fma2(acc[2][1], w2, d1);
            fma2(acc[2][2], w2, d2); fma2(acc[2][3], w2, d3);
        }

        float* outp = g_gx + ((size_t)t * GR + g) * ROWS * BATCH;
#pragma unroll
        for (int p = 0; p < 3; p++) {
#pragma unroll
            for (int i = 0; i < 4; i++) {
                float2 u = up(acc[p][i]);
                outp[(ro + 2 * p)     * BATCH + bq + 8 * i] = u.x;
                outp[(ro + 2 * p + 1) * BATCH + bq + 8 * i] = u.y;
            }
        }
    }
}

// ============================================================================
// Phase 2: recurrence. 128 CTAs = (g) x (bp), 512 threads: j = tid>>2,
// q = tid&3 (k-chunk of 32 in lane bits).
// r,z gate weights register-resident (32 ull = 64 regs); n-gate weights in
// smem, LANE-OWNED layout Wn[i][tid] -> coalesced conflict-free LDS.64, so
// total regs fit under the 128 cap (R4 spilled ~12 regs, reloaded per step).
// gx via cp.async triple-buffer ring; reduce-scatter shfl over q lanes;
// ping-pong h; one barrier per step.
// Dynamic smem: Wn 64KB | Gs 9KB | H 2.25KB = 77KB.
// ============================================================================
__global__ void __launch_bounds__(512, 1)
gru_kernel(const float* __restrict__ state,
           const float* __restrict__ W_hh,
           const float* __restrict__ b_hh,
           float* __restrict__ out)
{
    extern __shared__ char dynsm[];
    ull*   Wn = (ull*)dynsm;                        // [16][512]
    float* Gs = (float*)(dynsm + 65536);            // [3][ROWS*2]
    float* Hb = (float*)(dynsm + 65536 + 9216);     // [4][HPAD]: b0p0,b0p1,b1p0,b1p1

    const int g   = blockIdx.x >> 4;
    const int bp  = blockIdx.x & 15;
    const int tid = threadIdx.x;
    const int j   = tid >> 2;
    const int q   = tid & 3;
    const int b0  = bp * 2;

    // r,z weights -> registers; n weights -> smem lane-owned column
    ull wr[16], wz[16];
    {
        const float* base = W_hh + (size_t)g * ROWS * 128 + q * 32;
        const float* pr = base + (size_t)(j)       * 128;
        const float* pz = base + (size_t)(128 + j) * 128;
        const float* pn = base + (size_t)(256 + j) * 128;
#pragma unroll
        for (int i = 0; i < 8; i++) {
            ulonglong2 a = *(const ulonglong2*)(pr + i * 4);
            wr[2 * i] = a.x; wr[2 * i + 1] = a.y;
            ulonglong2 b = *(const ulonglong2*)(pz + i * 4);
            wz[2 * i] = b.x; wz[2 * i + 1] = b.y;
            ulonglong2 c = *(const ulonglong2*)(pn + i * 4);
            Wn[(2 * i)     * 512 + tid] = c.x;
            Wn[(2 * i + 1) * 512 + tid] = c.y;
        }
    }
    const ull* WnT = Wn + tid;

    const float bhr = b_hh[g * ROWS + j];
    const float bhz = b_hh[g * ROWS + 128 + j];
    const float bhn = b_hh[g * ROWS + 256 + j];

    const int jsw = (j >> 5) * 36 + (j & 31);

    if (q == 0) Hb[jsw]            = state[((size_t)g * 32 + b0) * 128 + j];
    if (q == 2) Hb[2 * HPAD + jsw] = state[((size_t)g * 32 + b0 + 1) * 128 + j];

    const size_t stride_t = (size_t)GR * ROWS * BATCH;
    const float* gx0 = g_gx + (size_t)g * ROWS * BATCH + b0;

    // prologue: stage gx for t=0 (buf0) and t=1 (buf1)
    const float* gxt = gx0 + (size_t)tid * BATCH;   // advanced by stride_t
    if (tid < ROWS) cpa8(sptr(&Gs[tid * 2]), gxt);
    cpcommit();
    if (tid < ROWS) cpa8(sptr(&Gs[768 + tid * 2]), gxt + stride_t);
    cpcommit();
    gxt += 2 * stride_t;
    cpwait1();
    __syncthreads();

    // per-thread out pointer for its batch (used by q==1 / q==3 lanes)
    const int myb = q >> 1;
    float* outp = out + ((size_t)(b0 + myb) * TT) * 1024 + g * 128 + j;

    const int qoff = q * 36;
    int p = 0, cb = 0;

    for (int t = 0; t < TT; t++) {
        // stage gx for t+2 into buffer (cb+2)%3
        {
            int nb = cb + 2; if (nb >= 3) nb -= 3;
            if (t + 2 < TT && tid < ROWS)
                cpa8(sptr(&Gs[nb * 768 + tid * 2]), gxt);
            cpcommit();
            gxt += stride_t;
        }

        const float* H0 = Hb + p * HPAD;
        const float* H1 = Hb + (2 + p) * HPAD;

        ull ar0 = 0, az0 = 0, an0 = 0;
        ull ar1 = 0, az1 = 0, an1 = 0;

#pragma unroll
        for (int i = 0; i < 8; i++) {
            ulonglong2 h0 = *(const ulonglong2*)(H0 + qoff + i * 4);
            ulonglong2 h1 = *(const ulonglong2*)(H1 + qoff + i * 4);
            ull wn0 = WnT[(2 * i) * 512];
            ull wn1 = WnT[(2 * i + 1) * 512];
            fma2(ar0, wr[2 * i],     h0.x);
            fma2(az0, wz[2 * i],     h0.x);
            fma2(an0, wn0,           h0.x);
            fma2(ar1, wr[2 * i],     h1.x);
            fma2(az1, wz[2 * i],     h1.x);
            fma2(an1, wn0,           h1.x);
            fma2(ar0, wr[2 * i + 1], h0.y);
            fma2(az0, wz[2 * i + 1], h0.y);
            fma2(an0, wn1,           h0.y);
            fma2(ar1, wr[2 * i + 1], h1.y);
            fma2(az1, wz[2 * i + 1], h1.y);
            fma2(an1, wn1,           h1.y);
        }

        // collapse packed halves
        float sr0 = hadd(ar0), sz0 = hadd(az0), sn0 = hadd(an0);
        float sr1 = hadd(ar1), sz1 = hadd(az1), sn1 = hadd(an1);

        // reduce-scatter over 4 q lanes: q<2 -> full b0 sums, q>=2 -> b1
        const bool hi = (q & 2) != 0;
        float vr = hi ? sr0 : sr1;
        float vz = hi ? sz0 : sz1;
        float vn = hi ? sn0 : sn1;
        float kr = hi ? sr1 : sr0;
        float kz = hi ? sz1 : sz0;
        float kn = hi ? sn1 : sn0;
        kr += __shfl_xor_sync(0xffffffffu, vr, 2);
        kz += __shfl_xor_sync(0xffffffffu, vz, 2);
        kn += __shfl_xor_sync(0xffffffffu, vn, 2);
        kr += __shfl_xor_sync(0xffffffffu, kr, 1);
        kz += __shfl_xor_sync(0xffffffffu, kz, 1);
        kn += __shfl_xor_sync(0xffffffffu, kn, 1);

        // my batch's gx + h_old
        const float* Gc = Gs + cb * 768;
        float gr_ = Gc[(j)       * 2 + myb];
        float gz_ = Gc[(128 + j) * 2 + myb];
        float gn_ = Gc[(256 + j) * 2 + myb];
        float hold = (hi ? H1 : H0)[jsw];

        float r = sigm(gr_ + kr + bhr);
        float z = sigm(gz_ + kz + bhz);
        float n = tanh_(gn_ + r * (kn + bhn));
        float hn = n + z * (hold - n);

        const int np = p ^ 1;
        if (q == 0) {
            Hb[np * HPAD + jsw] = hn;
        } else if (q == 2) {
            Hb[(2 + np) * HPAD + jsw] = hn;
        } else {
            *outp = hn;
        }
        outp += 1024;

        cpwait1();
        __syncthreads();
        p = np;
        cb = cb + 1; if (cb >= 3) cb -= 3;
    }

    // h_out[g][b][j] appended after y
    float* hop = out + (size_t)BATCH * TT * 1024;
    if (q == 0) hop[((size_t)g * 32 + b0) * 128 + j]     = Hb[p * HPAD + jsw];
    if (q == 2) hop[((size_t)g * 32 + b0 + 1) * 128 + j] = Hb[(2 + p) * HPAD + jsw];
}

extern "C" void kernel_launch(void* const* d_in, const int* in_sizes, int n_in,
                              void* d_out, int out_size)
{
    const float* x     = (const float*)d_in[0];
    const float* state = (const float*)d_in[1];
    const float* W_ih  = (const float*)d_in[2];
    const float* W_hh  = (const float*)d_in[3];
    const float* b_ih  = (const float*)d_in[4];
    const float* b_hh  = (const float*)d_in[5];
    float* out = (float*)d_out;

    const int smem1 = (128 * PADW + 2 * 32 * XROW) * 4;   // 231,424 B
    const int smem2 = 65536 + 9216 + 4 * HPAD * 4;        // 77,056 B

    cudaFuncSetAttribute(gx_kernel,  cudaFuncAttributeMaxDynamicSharedMemorySize, smem1);
    cudaFuncSetAttribute(gru_kernel, cudaFuncAttributeMaxDynamicSharedMemorySize, smem2);

    gx_kernel<<<128, 512, smem1>>>(x, W_ih, b_ih);
    gru_kernel<<<128, 512, smem2>>>(state, W_hh, b_hh, out);
}